// round 1
// baseline (speedup 1.0000x reference)
#include <cuda_runtime.h>
#include <cstddef>

// Problem constants
#define SEQ   512
#define BATCH 4096
#define INDIM 9
#define HID   64
#define OUTD  10
#define NTHREADS 192   // warps 0-1: layer1, warps 2-3: layer2, warps 4-5: prologue/epilogue help

// Shared memory layout (floats):
//  xwbuf : SEQ*HID   (32768)  precomputed xw1; slot t overwritten with h2[t] after use
//  xs    : SEQ*INDIM (4608)   x[:, BATCH-1, :]
//  h1buf : 2*HID     (128)    double-buffered layer1 hidden
//  h2buf : 2*HID     (128)    double-buffered layer2 hidden
//  wfc   : OUTD*HID  (640)
//  bfc   : 16        (pad)
#define SM_FLOATS (SEQ*HID + SEQ*INDIM + 2*HID + 2*HID + OUTD*HID + 16)
#define SM_BYTES  (SM_FLOATS * 4)

__device__ __forceinline__ unsigned long long ffma2(unsigned long long a,
                                                    unsigned long long b,
                                                    unsigned long long c) {
    unsigned long long d;
    asm("fma.rn.f32x2 %0, %1, %2, %3;" : "=l"(d) : "l"(a), "l"(b), "l"(c));
    return d;
}

__device__ __forceinline__ float f2sum(unsigned long long a) {
    float2 f = *reinterpret_cast<float2*>(&a);
    return f.x + f.y;
}

__global__ __launch_bounds__(NTHREADS, 1)
void rnn_motion_kernel(const float* __restrict__ x,
                       const float* __restrict__ Wih0, const float* __restrict__ Whh0,
                       const float* __restrict__ bih0, const float* __restrict__ bhh0,
                       const float* __restrict__ Wih1, const float* __restrict__ Whh1,
                       const float* __restrict__ bih1, const float* __restrict__ bhh1,
                       const float* __restrict__ Wfc,  const float* __restrict__ bfc_g,
                       float* __restrict__ out)
{
    extern __shared__ float sm[];
    float* xwbuf = sm;                       // SEQ*HID
    float* xs    = xwbuf + SEQ*HID;          // SEQ*INDIM
    float* h1buf = xs + SEQ*INDIM;           // 2*HID
    float* h2buf = h1buf + 2*HID;            // 2*HID
    float* wfc   = h2buf + 2*HID;            // OUTD*HID
    float* bfc   = wfc + OUTD*HID;           // OUTD

    const int tid = threadIdx.x;

    // ---------------- Prologue stage A: gather x[:, B-1, :], W_fc, b_fc; zero h ----
    for (int e = tid; e < SEQ*INDIM; e += NTHREADS) {
        int t = e / INDIM, k = e % INDIM;
        xs[e] = x[((size_t)t * BATCH + (BATCH - 1)) * INDIM + k];
    }
    for (int e = tid; e < OUTD*HID; e += NTHREADS) wfc[e] = Wfc[e];
    if (tid < OUTD) bfc[tid] = bfc_g[tid];
    for (int e = tid; e < 4*HID; e += NTHREADS) h1buf[e] = 0.0f;  // h1buf+h2buf contiguous
    __syncthreads();

    // ---------------- Prologue stage B: xw1[t][i] = x_t . Wih0[i] + b_ih0[i]+b_hh0[i]
    {
        const int i = tid % HID;          // fixed per thread (192 % 64 == 0)
        float wi[INDIM];
        #pragma unroll
        for (int k = 0; k < INDIM; ++k) wi[k] = Wih0[i*INDIM + k];
        const float bb = bih0[i] + bhh0[i];
        for (int t = tid / HID; t < SEQ; t += NTHREADS / HID) {
            float s = bb;
            #pragma unroll
            for (int k = 0; k < INDIM; ++k) s += xs[t*INDIM + k] * wi[k];
            xwbuf[t*HID + i] = s;
        }
    }
    __syncthreads();

    // ---------------- Main scan: 513 skewed iterations, one barrier each ------------
    if (tid < HID) {
        // ===== layer1: thread i computes h1[it][i] =====
        const int i = tid;
        unsigned long long wA[HID/2];
        {
            const ulonglong2* wp = reinterpret_cast<const ulonglong2*>(Whh0 + (size_t)i*HID);
            #pragma unroll
            for (int q = 0; q < HID/4; ++q) { ulonglong2 v = wp[q]; wA[2*q] = v.x; wA[2*q+1] = v.y; }
        }
        for (int it = 0; it <= SEQ; ++it) {
            const int r = it & 1, w = r ^ 1;
            if (it < SEQ) {
                unsigned long long a0 = 0ull, a1 = 0ull, a2 = 0ull, a3 = 0ull;
                const ulonglong2* hp = reinterpret_cast<const ulonglong2*>(h1buf + r*HID);
                #pragma unroll
                for (int q = 0; q < HID/4; q += 2) {
                    ulonglong2 v0 = hp[q];
                    ulonglong2 v1 = hp[q+1];
                    a0 = ffma2(v0.x, wA[2*q],   a0);
                    a1 = ffma2(v0.y, wA[2*q+1], a1);
                    a2 = ffma2(v1.x, wA[2*q+2], a2);
                    a3 = ffma2(v1.y, wA[2*q+3], a3);
                }
                float s = xwbuf[it*HID + i] + f2sum(a0) + f2sum(a1) + f2sum(a2) + f2sum(a3);
                h1buf[w*HID + i] = tanhf(s);
            }
            __syncthreads();
        }
    } else if (tid < 2*HID) {
        // ===== layer2 (1-step skew): at iter it computes h2[it-1][i] =====
        const int i = tid - HID;
        unsigned long long wI[HID/2], wH[HID/2];
        {
            const ulonglong2* wp = reinterpret_cast<const ulonglong2*>(Wih1 + (size_t)i*HID);
            #pragma unroll
            for (int q = 0; q < HID/4; ++q) { ulonglong2 v = wp[q]; wI[2*q] = v.x; wI[2*q+1] = v.y; }
            const ulonglong2* wq = reinterpret_cast<const ulonglong2*>(Whh1 + (size_t)i*HID);
            #pragma unroll
            for (int q = 0; q < HID/4; ++q) { ulonglong2 v = wq[q]; wH[2*q] = v.x; wH[2*q+1] = v.y; }
        }
        const float bias2 = bih1[i] + bhh1[i];
        for (int it = 0; it <= SEQ; ++it) {
            const int r = it & 1, w = r ^ 1;
            if (it >= 1) {
                // h1buf[r] holds h1[it-1]; h2buf[r] holds h2[it-2]
                unsigned long long a0 = 0ull, a1 = 0ull, b0 = 0ull, b1 = 0ull;
                const ulonglong2* hp1 = reinterpret_cast<const ulonglong2*>(h1buf + r*HID);
                const ulonglong2* hp2 = reinterpret_cast<const ulonglong2*>(h2buf + r*HID);
                #pragma unroll
                for (int q = 0; q < HID/4; ++q) {
                    ulonglong2 v1 = hp1[q];
                    ulonglong2 v2 = hp2[q];
                    a0 = ffma2(v1.x, wI[2*q],   a0);
                    a1 = ffma2(v1.y, wI[2*q+1], a1);
                    b0 = ffma2(v2.x, wH[2*q],   b0);
                    b1 = ffma2(v2.y, wH[2*q+1], b1);
                }
                float s = bias2 + f2sum(a0) + f2sum(a1) + f2sum(b0) + f2sum(b1);
                float hv = tanhf(s);
                h2buf[w*HID + i]        = hv;
                xwbuf[(it-1)*HID + i]   = hv;   // slot (it-1) already consumed by layer1
            }
            __syncthreads();
        }
    } else {
        // ===== helper warps: keep barrier counts aligned =====
        for (int it = 0; it <= SEQ; ++it) __syncthreads();
    }

    // ---------------- Epilogue: out[t][o] = h2[t] . Wfc[o] + b_fc[o] ----------------
    for (int n = tid; n < SEQ*OUTD; n += NTHREADS) {
        const int t = n / OUTD, o = n % OUTD;
        const float* h2 = xwbuf + t*HID;
        const float* wr = wfc + o*HID;
        float s = bfc[o];
        #pragma unroll
        for (int k = 0; k < HID; ++k) s += h2[k] * wr[k];
        out[n] = s;
    }
}

extern "C" void kernel_launch(void* const* d_in, const int* in_sizes, int n_in,
                              void* d_out, int out_size) {
    (void)in_sizes; (void)n_in; (void)out_size;
    const float* x    = (const float*)d_in[0];
    const float* Wih0 = (const float*)d_in[1];
    const float* Whh0 = (const float*)d_in[2];
    const float* bih0 = (const float*)d_in[3];
    const float* bhh0 = (const float*)d_in[4];
    const float* Wih1 = (const float*)d_in[5];
    const float* Whh1 = (const float*)d_in[6];
    const float* bih1 = (const float*)d_in[7];
    const float* bhh1 = (const float*)d_in[8];
    const float* Wfc  = (const float*)d_in[9];
    const float* bfc  = (const float*)d_in[10];
    float* out = (float*)d_out;

    cudaFuncSetAttribute(rnn_motion_kernel,
                         cudaFuncAttributeMaxDynamicSharedMemorySize, SM_BYTES);
    rnn_motion_kernel<<<1, NTHREADS, SM_BYTES>>>(
        x, Wih0, Whh0, bih0, bhh0, Wih1, Whh1, bih1, bhh1, Wfc, bfc, out);
}